// round 1
// baseline (speedup 1.0000x reference)
#include <cuda_runtime.h>
#include <stdint.h>

#define N_EXPERTS 20
#define DIM 32
#define MAXB (1 << 17)   // 131072
#define TPB 256

// ---------------- device scratch (no allocations allowed) ----------------
__device__ int g_is64;                 // pos dtype flag: 1 = int64, 0 = int32
__device__ int g_counts[N_EXPERTS];
__device__ int g_cursor[N_EXPERTS];
__device__ int g_perm[MAXB];           // packed: (expert<<24) | token

__device__ __forceinline__ int load_pos(const void* pos, int t, int is64) {
    if (is64) return (int)((const long long*)pos)[t];
    return ((const int*)pos)[t];
}

// ---- kernel 0: zero counters + detect pos element width -----------------
// If pos is int64 (little-endian), every odd int32 slot is a high word == 0
// (values are in [0,20)). If pos is int32, the odd slots are random expert
// ids; P(all 32 == 0) = (1/20)^32 ~ 0.
__global__ void k_init(const void* pos, int B) {
    int tid = threadIdx.x;
    if (tid < N_EXPERTS) g_counts[tid] = 0;
    if (tid < 32) {
        int v = ((const int*)pos)[2 * tid + 1];   // needs B >= 64 (B = 131072)
        unsigned nz = __ballot_sync(0xffffffffu, v != 0);
        if (tid == 0) g_is64 = (nz == 0) ? 1 : 0;
    }
}

// ---- kernel 1: per-expert histogram (smem-aggregated) -------------------
__global__ void k_hist(const void* __restrict__ pos, int B) {
    __shared__ int sh[N_EXPERTS];
    if (threadIdx.x < N_EXPERTS) sh[threadIdx.x] = 0;
    __syncthreads();
    int t = blockIdx.x * blockDim.x + threadIdx.x;
    int is64 = g_is64;
    if (t < B) {
        int e = load_pos(pos, t, is64);
        atomicAdd(&sh[e], 1);
    }
    __syncthreads();
    if (threadIdx.x < N_EXPERTS && sh[threadIdx.x])
        atomicAdd(&g_counts[threadIdx.x], sh[threadIdx.x]);
}

// ---- kernel 2: exclusive scan of 20 counts (one warp) -------------------
__global__ void k_scan() {
    int i = threadIdx.x;
    int v = (i < N_EXPERTS) ? g_counts[i] : 0;
    int s = v;
    #pragma unroll
    for (int d = 1; d < 32; d <<= 1) {
        int u = __shfl_up_sync(0xffffffffu, s, d);
        if (i >= d) s += u;
    }
    if (i < N_EXPERTS) g_cursor[i] = s - v;   // exclusive prefix -> cursor
}

// ---- kernel 3: scatter tokens into expert buckets -----------------------
__global__ void k_scatter(const void* __restrict__ pos, int B) {
    __shared__ int sh[N_EXPERTS];
    __shared__ int sbase[N_EXPERTS];
    if (threadIdx.x < N_EXPERTS) sh[threadIdx.x] = 0;
    __syncthreads();
    int t = blockIdx.x * blockDim.x + threadIdx.x;
    int is64 = g_is64;
    int e = 0, r = 0;
    bool valid = (t < B);
    if (valid) {
        e = load_pos(pos, t, is64);
        r = atomicAdd(&sh[e], 1);
    }
    __syncthreads();
    if (threadIdx.x < N_EXPERTS) {
        int c = sh[threadIdx.x];
        sbase[threadIdx.x] = c ? atomicAdd(&g_cursor[threadIdx.x], c) : 0;
    }
    __syncthreads();
    if (valid) g_perm[sbase[e] + r] = (e << 24) | t;
}

// ---- kernel 4: main compute --------------------------------------------
// One thread = one token. CTA covers TPB consecutive sorted slots, which
// span at most 2 experts (min bucket size ~6300 >> TPB); those experts'
// weights are staged in SMEM so weight reads are broadcast loads.
__global__ void __launch_bounds__(TPB) k_compute(
    const float* __restrict__ x,
    const float* __restrict__ W1, const float* __restrict__ b1,
    const float* __restrict__ W0, const float* __restrict__ b0,
    float* __restrict__ out, int B)
{
    __shared__ __align__(16) float sW1[2][DIM * DIM];
    __shared__ __align__(16) float sW0[2][DIM * DIM];
    __shared__ __align__(16) float sb1[2][DIM];
    __shared__ __align__(16) float sb0[2][DIM];

    int tid  = threadIdx.x;
    int s0   = blockIdx.x * TPB;
    int send = min(s0 + TPB, B) - 1;
    int e0 = g_perm[s0]   >> 24;
    int e1 = g_perm[send] >> 24;

    for (int idx = tid; idx < DIM * DIM; idx += TPB) {
        sW1[0][idx] = W1[e0 * DIM * DIM + idx];
        sW0[0][idx] = W0[e0 * DIM * DIM + idx];
        if (e1 != e0) {
            sW1[1][idx] = W1[e1 * DIM * DIM + idx];
            sW0[1][idx] = W0[e1 * DIM * DIM + idx];
        }
    }
    if (tid < DIM) {
        sb1[0][tid] = b1[e0 * DIM + tid];
        sb0[0][tid] = b0[e0 * DIM + tid];
        if (e1 != e0) {
            sb1[1][tid] = b1[e1 * DIM + tid];
            sb0[1][tid] = b0[e1 * DIM + tid];
        }
    }
    __syncthreads();

    int slot = s0 + tid;
    if (slot >= B) return;

    int pv = g_perm[slot];
    int t  = pv & 0xFFFFFF;
    int e  = pv >> 24;

    const float *w1, *w0, *pb1, *pb0;
    if (e == e0)      { w1 = sW1[0]; w0 = sW0[0]; pb1 = sb1[0]; pb0 = sb0[0]; }
    else if (e == e1) { w1 = sW1[1]; w0 = sW0[1]; pb1 = sb1[1]; pb0 = sb0[1]; }
    else {   // pathological fallback (bucket smaller than TPB)
        w1 = W1 + e * DIM * DIM; w0 = W0 + e * DIM * DIM;
        pb1 = b1 + e * DIM;      pb0 = b0 + e * DIM;
    }

    // load token row
    float xr[DIM];
    const float4* xp = (const float4*)(x + (size_t)t * DIM);
    #pragma unroll
    for (int j = 0; j < DIM / 4; j++) {
        float4 v = xp[j];
        xr[4*j+0] = v.x; xr[4*j+1] = v.y; xr[4*j+2] = v.z; xr[4*j+3] = v.w;
    }

    // layer 1: h = x @ W1^T + b1
    float h[DIM];
    #pragma unroll
    for (int o = 0; o < DIM; o++) {
        float acc = pb1[o];
        const float4* wp = (const float4*)(w1 + o * DIM);
        #pragma unroll
        for (int j = 0; j < DIM / 4; j++) {
            float4 wv = wp[j];
            acc = fmaf(xr[4*j+0], wv.x, acc);
            acc = fmaf(xr[4*j+1], wv.y, acc);
            acc = fmaf(xr[4*j+2], wv.z, acc);
            acc = fmaf(xr[4*j+3], wv.w, acc);
        }
        h[o] = acc;
    }

    // layer 0: out = h @ W0^T + b0, accumulate squared norm
    float ov[DIM];
    float ss = 0.0f;
    #pragma unroll
    for (int o = 0; o < DIM; o++) {
        float acc = pb0[o];
        const float4* wp = (const float4*)(w0 + o * DIM);
        #pragma unroll
        for (int j = 0; j < DIM / 4; j++) {
            float4 wv = wp[j];
            acc = fmaf(h[4*j+0], wv.x, acc);
            acc = fmaf(h[4*j+1], wv.y, acc);
            acc = fmaf(h[4*j+2], wv.z, acc);
            acc = fmaf(h[4*j+3], wv.w, acc);
        }
        ov[o] = acc;
        ss = fmaf(acc, acc, ss);
    }

    float nrm = sqrtf(ss);
    float inv = 1.0f / fmaxf(nrm, 1e-12f);

    float4* op = (float4*)(out + (size_t)t * DIM);
    #pragma unroll
    for (int j = 0; j < DIM / 4; j++) {
        float4 v;
        v.x = ov[4*j+0] * inv; v.y = ov[4*j+1] * inv;
        v.z = ov[4*j+2] * inv; v.w = ov[4*j+3] * inv;
        op[j] = v;
    }
}

// ---------------- launch -------------------------------------------------
extern "C" void kernel_launch(void* const* d_in, const int* in_sizes, int n_in,
                              void* d_out, int out_size) {
    const float* x  = (const float*)d_in[0];
    const float* W1 = (const float*)d_in[1];
    const float* b1 = (const float*)d_in[2];
    const float* W0 = (const float*)d_in[3];
    const float* b0 = (const float*)d_in[4];
    const void*  pos = d_in[5];
    float* out = (float*)d_out;

    int B = in_sizes[0] / DIM;
    if (B > MAXB) B = MAXB;
    int nblk = (B + TPB - 1) / TPB;

    k_init<<<1, 32>>>(pos, B);
    k_hist<<<nblk, TPB>>>(pos, B);
    k_scan<<<1, 32>>>();
    k_scatter<<<nblk, TPB>>>(pos, B);
    k_compute<<<nblk, TPB>>>(x, W1, b1, W0, b0, out, B);
}

// round 2
// speedup vs baseline: 1.1621x; 1.1621x over previous
#include <cuda_runtime.h>
#include <stdint.h>

#define N_EXPERTS 20
#define DIM 32
#define MAXB (1 << 17)   // 131072
#define TPB 256

typedef unsigned long long u64;

// ---------------- device scratch (no allocations allowed) ----------------
__device__ int g_cnt[N_EXPERTS];
__device__ int g_bucket[N_EXPERTS * MAXB];   // fixed-capacity per-expert regions

// ---------------- packed f32x2 helpers (sm_103a dual-issue fp32) ---------
__device__ __forceinline__ u64 pk2(float lo, float hi) {
    u64 r; asm("mov.b64 %0, {%1, %2};" : "=l"(r) : "f"(lo), "f"(hi)); return r;
}
__device__ __forceinline__ void unpk2(u64 v, float& lo, float& hi) {
    asm("mov.b64 {%0, %1}, %2;" : "=f"(lo), "=f"(hi) : "l"(v));
}
__device__ __forceinline__ u64 fma2(u64 a, u64 b, u64 c) {
    u64 d; asm("fma.rn.f32x2 %0, %1, %2, %3;" : "=l"(d) : "l"(a), "l"(b), "l"(c)); return d;
}

// ---- kernel 0: zero per-expert counters ---------------------------------
__global__ void k_init() {
    if (threadIdx.x < N_EXPERTS) g_cnt[threadIdx.x] = 0;
}

// ---- kernel 1: fused bucket (hist + base-claim + write, one pass) -------
// pos dtype (int32 vs int64) detected per block: if int64 little-endian,
// all odd int32 slots are zero high-words (values in [0,20)).
__global__ void k_bucket(const void* __restrict__ pos, int B) {
    __shared__ int sh[N_EXPERTS];
    __shared__ int sbase[N_EXPERTS];
    __shared__ int s_is64;

    if (threadIdx.x < N_EXPERTS) sh[threadIdx.x] = 0;
    if (threadIdx.x < 32) {
        int v = ((const int*)pos)[2 * threadIdx.x + 1];   // B >= 64 guaranteed
        unsigned nz = __ballot_sync(0xffffffffu, v != 0);
        if (threadIdx.x == 0) s_is64 = (nz == 0) ? 1 : 0;
    }
    __syncthreads();

    int t = blockIdx.x * blockDim.x + threadIdx.x;
    bool valid = (t < B);
    int e = 0, r = 0;
    if (valid) {
        e = s_is64 ? (int)((const long long*)pos)[t] : ((const int*)pos)[t];
        r = atomicAdd(&sh[e], 1);
    }
    __syncthreads();
    if (threadIdx.x < N_EXPERTS) {
        int c = sh[threadIdx.x];
        sbase[threadIdx.x] = c ? atomicAdd(&g_cnt[threadIdx.x], c) : 0;
    }
    __syncthreads();
    if (valid) g_bucket[e * MAXB + sbase[e] + r] = t;
}

// ---- kernel 2: main compute (single-expert CTAs, f32x2 math) ------------
// grid = (ceil(B/TPB), N_EXPERTS). Blocks past their expert's count exit.
__global__ void __launch_bounds__(TPB) k_compute(
    const float* __restrict__ x,
    const float* __restrict__ W1, const float* __restrict__ b1,
    const float* __restrict__ W0, const float* __restrict__ b0,
    float* __restrict__ out)
{
    __shared__ __align__(16) float sW1[DIM * DIM];
    __shared__ __align__(16) float sW0[DIM * DIM];
    __shared__ float sb1[DIM];
    __shared__ float sb0[DIM];

    int e = blockIdx.y;
    int n = g_cnt[e];
    int base = blockIdx.x * TPB;
    if (base >= n) return;

    for (int i = threadIdx.x; i < DIM * DIM; i += TPB) {
        sW1[i] = W1[e * DIM * DIM + i];
        sW0[i] = W0[e * DIM * DIM + i];
    }
    if (threadIdx.x < DIM) {
        sb1[threadIdx.x] = b1[e * DIM + threadIdx.x];
        sb0[threadIdx.x] = b0[e * DIM + threadIdx.x];
    }
    __syncthreads();

    int slot = base + threadIdx.x;
    if (slot >= n) return;
    int t = g_bucket[e * MAXB + slot];

    // load token row, packed as 16 f32x2 (k, k+1) pairs
    u64 xr[DIM / 2];
    {
        const ulonglong2* xp = (const ulonglong2*)(x + (size_t)t * DIM);
        #pragma unroll
        for (int j = 0; j < DIM / 4; j++) {
            ulonglong2 v = xp[j];
            xr[2 * j] = v.x; xr[2 * j + 1] = v.y;
        }
    }

    // layer 1: h = x @ W1^T + b1   (K packed into f32x2 halves)
    float h[DIM];
    #pragma unroll
    for (int o = 0; o < DIM; o++) {
        const ulonglong2* wp = (const ulonglong2*)(sW1 + o * DIM);
        u64 acc = pk2(sb1[o], 0.0f);
        #pragma unroll
        for (int j = 0; j < DIM / 4; j++) {
            ulonglong2 w = wp[j];
            acc = fma2(w.x, xr[2 * j], acc);
            acc = fma2(w.y, xr[2 * j + 1], acc);
        }
        float lo, hi; unpk2(acc, lo, hi);
        h[o] = lo + hi;
    }

    // repack h
    u64 hr[DIM / 2];
    #pragma unroll
    for (int j = 0; j < DIM / 2; j++) hr[j] = pk2(h[2 * j], h[2 * j + 1]);

    // layer 0: out = h @ W0^T + b0, accumulate squared norm
    float ov[DIM];
    float ss = 0.0f;
    #pragma unroll
    for (int o = 0; o < DIM; o++) {
        const ulonglong2* wp = (const ulonglong2*)(sW0 + o * DIM);
        u64 acc = pk2(sb0[o], 0.0f);
        #pragma unroll
        for (int j = 0; j < DIM / 4; j++) {
            ulonglong2 w = wp[j];
            acc = fma2(w.x, hr[2 * j], acc);
            acc = fma2(w.y, hr[2 * j + 1], acc);
        }
        float lo, hi; unpk2(acc, lo, hi);
        float v = lo + hi;
        ov[o] = v;
        ss = fmaf(v, v, ss);
    }

    float inv = 1.0f / fmaxf(sqrtf(ss), 1e-12f);

    float4* op = (float4*)(out + (size_t)t * DIM);
    #pragma unroll
    for (int j = 0; j < DIM / 4; j++) {
        float4 v;
        v.x = ov[4 * j + 0] * inv; v.y = ov[4 * j + 1] * inv;
        v.z = ov[4 * j + 2] * inv; v.w = ov[4 * j + 3] * inv;
        op[j] = v;
    }
}

// ---------------- launch -------------------------------------------------
extern "C" void kernel_launch(void* const* d_in, const int* in_sizes, int n_in,
                              void* d_out, int out_size) {
    const float* x  = (const float*)d_in[0];
    const float* W1 = (const float*)d_in[1];
    const float* b1 = (const float*)d_in[2];
    const float* W0 = (const float*)d_in[3];
    const float* b0 = (const float*)d_in[4];
    const void*  pos = d_in[5];
    float* out = (float*)d_out;

    int B = in_sizes[0] / DIM;
    if (B > MAXB) B = MAXB;
    int nblk = (B + TPB - 1) / TPB;

    k_init<<<1, 32>>>();
    k_bucket<<<nblk, TPB>>>(pos, B);
    dim3 grid(nblk, N_EXPERTS);
    k_compute<<<grid, TPB>>>(x, W1, b1, W0, b0, out);
}

// round 3
// speedup vs baseline: 1.2343x; 1.0622x over previous
#include <cuda_runtime.h>
#include <stdint.h>

#define N_EXPERTS 20
#define DIM 32
#define MAXB (1 << 17)   // 131072
#define TPB 256
#define PAD 36           // tile row stride in floats (16B-aligned rows, bounded conflicts)

typedef unsigned long long u64;

// ---------------- device scratch (no allocations allowed) ----------------
__device__ int g_cnt[N_EXPERTS];
__device__ int g_bucket[N_EXPERTS * MAXB];   // fixed-capacity per-expert regions

// ---------------- packed f32x2 helpers -----------------------------------
__device__ __forceinline__ u64 pk2(float lo, float hi) {
    u64 r; asm("mov.b64 %0, {%1, %2};" : "=l"(r) : "f"(lo), "f"(hi)); return r;
}
__device__ __forceinline__ void unpk2(u64 v, float& lo, float& hi) {
    asm("mov.b64 {%0, %1}, %2;" : "=f"(lo), "=f"(hi) : "l"(v));
}
__device__ __forceinline__ u64 fma2(u64 a, u64 b, u64 c) {
    u64 d; asm("fma.rn.f32x2 %0, %1, %2, %3;" : "=l"(d) : "l"(a), "l"(b), "l"(c)); return d;
}

// ---- kernel 1: fused bucket (warp-aggregated hist + claim + write) ------
__global__ void __launch_bounds__(TPB) k_bucket(const void* __restrict__ pos, int B) {
    __shared__ int sh[N_EXPERTS];
    __shared__ int sbase[N_EXPERTS];
    __shared__ int s_is64;

    if (threadIdx.x < N_EXPERTS) sh[threadIdx.x] = 0;
    if (threadIdx.x < 32) {
        // int64 pos => all odd 32-bit words are zero high-words (values < 20)
        int v = ((const int*)pos)[2 * threadIdx.x + 1];   // B >= 64 guaranteed
        unsigned nz = __ballot_sync(0xffffffffu, v != 0);
        if (threadIdx.x == 0) s_is64 = (nz == 0) ? 1 : 0;
    }
    __syncthreads();

    int t = blockIdx.x * TPB + threadIdx.x;
    bool valid = (t < B);
    int e = valid
          ? (s_is64 ? (int)((const long long*)pos)[t] : ((const int*)pos)[t])
          : -1;

    // warp-aggregated smem histogram: one atomic per distinct expert per warp
    unsigned mm = __match_any_sync(0xffffffffu, e);
    int lane = threadIdx.x & 31;
    int rank = __popc(mm & ((1u << lane) - 1));
    int leader = __ffs(mm) - 1;
    int wbase = 0;
    if (lane == leader && valid) wbase = atomicAdd(&sh[e], __popc(mm));
    wbase = __shfl_sync(0xffffffffu, wbase, leader);
    int r = wbase + rank;

    __syncthreads();
    if (threadIdx.x < N_EXPERTS) {
        int c = sh[threadIdx.x];
        sbase[threadIdx.x] = c ? atomicAdd(&g_cnt[threadIdx.x], c) : 0;
    }
    __syncthreads();
    if (valid) g_bucket[e * MAXB + sbase[e] + r] = t;
}

// ---- kernel 2: main compute ---------------------------------------------
// Exact 1-D grid: block walks per-expert block counts to find (expert, tile).
// Coalesced staging of x into SMEM, packed f32x2 matvecs, unscaled outputs
// back into the same tile + per-token inv scale applied during the
// coalesced store.
__global__ void __launch_bounds__(TPB) k_compute(
    const float* __restrict__ x,
    const float* __restrict__ W1, const float* __restrict__ b1,
    const float* __restrict__ W0, const float* __restrict__ b0,
    float* __restrict__ out)
{
    __shared__ __align__(16) float tile[TPB * PAD];       // 36 KB
    __shared__ __align__(16) float sW1[DIM * DIM];
    __shared__ __align__(16) float sW0[DIM * DIM];
    __shared__ float sb1[DIM], sb0[DIM];
    __shared__ float sInv[TPB];

    // ---- block -> (expert, tile) mapping (broadcast reads, 20 iters) ----
    int rem = blockIdx.x;
    int e = 0, n = 0;
    #pragma unroll 1
    for (e = 0; e < N_EXPERTS; e++) {
        n = g_cnt[e];
        int nb = (n + TPB - 1) / TPB;
        if (rem < nb) break;
        rem -= nb;
    }
    if (e == N_EXPERTS) return;   // uniform exit, before any __syncthreads
    int base = rem * TPB;

    int tid  = threadIdx.x;
    int lane = tid & 31;
    int w    = tid >> 5;

    // ---- stage weights ----
    #pragma unroll
    for (int i = tid; i < DIM * DIM; i += TPB) {
        sW1[i] = W1[e * DIM * DIM + i];
        sW0[i] = W0[e * DIM * DIM + i];
    }
    if (tid < DIM) {
        sb1[tid] = b1[e * DIM + tid];
        sb0[tid] = b0[e * DIM + tid];
    }

    // ---- coalesced x staging: warp-per-row ----
    int slot = base + tid;
    int tok  = (slot < n) ? g_bucket[e * MAXB + slot] : -1;
    #pragma unroll 1
    for (int i = 0; i < 32; i++) {
        int t = __shfl_sync(0xffffffffu, tok, i);
        if (t >= 0) tile[(w * 32 + i) * PAD + lane] = x[(size_t)t * DIM + lane];
    }
    __syncthreads();

    bool act = (slot < n);
    if (act) {
        // x row -> registers as 16 f32x2 pairs
        u64 xr[DIM / 2];
        {
            const ulonglong2* xp = (const ulonglong2*)(tile + tid * PAD);
            #pragma unroll
            for (int j = 0; j < DIM / 4; j++) {
                ulonglong2 v = xp[j];
                xr[2 * j] = v.x; xr[2 * j + 1] = v.y;
            }
        }

        // layer 1: h = x @ W1^T + b1, computed pairwise into packed hr
        u64 hr[DIM / 2];
        #pragma unroll
        for (int p = 0; p < DIM / 2; p++) {
            const ulonglong2* wa = (const ulonglong2*)(sW1 + (2 * p)     * DIM);
            const ulonglong2* wb = (const ulonglong2*)(sW1 + (2 * p + 1) * DIM);
            u64 acc0 = pk2(sb1[2 * p],     0.0f);
            u64 acc1 = pk2(sb1[2 * p + 1], 0.0f);
            #pragma unroll
            for (int j = 0; j < DIM / 4; j++) {
                ulonglong2 a = wa[j], b = wb[j];
                acc0 = fma2(a.x, xr[2 * j],     acc0);
                acc1 = fma2(b.x, xr[2 * j],     acc1);
                acc0 = fma2(a.y, xr[2 * j + 1], acc0);
                acc1 = fma2(b.y, xr[2 * j + 1], acc1);
            }
            float l0, h0, l1, h1;
            unpk2(acc0, l0, h0); unpk2(acc1, l1, h1);
            hr[p] = pk2(l0 + h0, l1 + h1);
        }

        // layer 0: out = h @ W0^T + b0 (unscaled into tile), accumulate ss
        float ss = 0.0f;
        float* orow = tile + tid * PAD;
        #pragma unroll
        for (int p = 0; p < DIM / 2; p++) {
            const ulonglong2* wa = (const ulonglong2*)(sW0 + (2 * p)     * DIM);
            const ulonglong2* wb = (const ulonglong2*)(sW0 + (2 * p + 1) * DIM);
            u64 acc0 = pk2(sb0[2 * p],     0.0f);
            u64 acc1 = pk2(sb0[2 * p + 1], 0.0f);
            #pragma unroll
            for (int j = 0; j < DIM / 4; j++) {
                ulonglong2 a = wa[j], b = wb[j];
                acc0 = fma2(a.x, hr[2 * j],     acc0);
                acc1 = fma2(b.x, hr[2 * j],     acc1);
                acc0 = fma2(a.y, hr[2 * j + 1], acc0);
                acc1 = fma2(b.y, hr[2 * j + 1], acc1);
            }
            float l0, h0, l1, h1;
            unpk2(acc0, l0, h0); unpk2(acc1, l1, h1);
            float v0 = l0 + h0, v1 = l1 + h1;
            ss = fmaf(v0, v0, ss);
            ss = fmaf(v1, v1, ss);
            orow[2 * p]     = v0;
            orow[2 * p + 1] = v1;
        }
        sInv[tid] = 1.0f / fmaxf(sqrtf(ss), 1e-12f);
    }
    __syncthreads();

    // ---- coalesced scaled store: warp-per-row ----
    #pragma unroll 1
    for (int i = 0; i < 32; i++) {
        int t = __shfl_sync(0xffffffffu, tok, i);
        if (t >= 0) {
            int row = w * 32 + i;
            out[(size_t)t * DIM + lane] = tile[row * PAD + lane] * sInv[row];
        }
    }
}

// ---------------- launch -------------------------------------------------
extern "C" void kernel_launch(void* const* d_in, const int* in_sizes, int n_in,
                              void* d_out, int out_size) {
    const float* x  = (const float*)d_in[0];
    const float* W1 = (const float*)d_in[1];
    const float* b1 = (const float*)d_in[2];
    const float* W0 = (const float*)d_in[3];
    const float* b0 = (const float*)d_in[4];
    const void*  pos = d_in[5];
    float* out = (float*)d_out;

    int B = in_sizes[0] / DIM;
    if (B > MAXB) B = MAXB;
    int nblk = (B + TPB - 1) / TPB;

    // zero per-expert counters via a graph memset node (no kernel launch)
    void* cnt_ptr = nullptr;
    cudaGetSymbolAddress(&cnt_ptr, g_cnt);
    cudaMemsetAsync(cnt_ptr, 0, N_EXPERTS * sizeof(int), 0);

    k_bucket<<<nblk, TPB>>>(pos, B);
    // exact grid: sum over experts of ceil(cnt_e/TPB) <= nblk + N_EXPERTS - 1
    k_compute<<<nblk + N_EXPERTS - 1, TPB>>>(x, W1, b1, W0, b0, out);
}

// round 4
// speedup vs baseline: 1.3741x; 1.1133x over previous
#include <cuda_runtime.h>
#include <stdint.h>

#define N_EXPERTS 20
#define DIM 32
#define MAXB (1 << 17)   // 131072
#define TPB 256

typedef unsigned long long u64;

// ---------------- device scratch (no allocations allowed) ----------------
__device__ int g_cnt[N_EXPERTS];
__device__ int g_bucket[N_EXPERTS * MAXB];   // fixed-capacity per-expert regions

// ---------------- packed f32x2 helpers -----------------------------------
__device__ __forceinline__ u64 pk2(float lo, float hi) {
    u64 r; asm("mov.b64 %0, {%1, %2};" : "=l"(r) : "f"(lo), "f"(hi)); return r;
}
__device__ __forceinline__ void unpk2(u64 v, float& lo, float& hi) {
    asm("mov.b64 {%0, %1}, %2;" : "=f"(lo), "=f"(hi) : "l"(v));
}
__device__ __forceinline__ u64 fma2(u64 a, u64 b, u64 c) {
    u64 d; asm("fma.rn.f32x2 %0, %1, %2, %3;" : "=l"(d) : "l"(a), "l"(b), "l"(c)); return d;
}

// ---- kernel 1: fused bucket (warp-aggregated hist + claim + write) ------
__global__ void __launch_bounds__(TPB) k_bucket(const void* __restrict__ pos, int B) {
    __shared__ int sh[N_EXPERTS];
    __shared__ int sbase[N_EXPERTS];
    __shared__ int s_is64;

    if (threadIdx.x < N_EXPERTS) sh[threadIdx.x] = 0;
    if (threadIdx.x < 32) {
        // int64 pos => all odd 32-bit words are zero high-words (values < 20)
        int v = ((const int*)pos)[2 * threadIdx.x + 1];   // B >= 64 guaranteed
        unsigned nz = __ballot_sync(0xffffffffu, v != 0);
        if (threadIdx.x == 0) s_is64 = (nz == 0) ? 1 : 0;
    }
    __syncthreads();

    int t = blockIdx.x * TPB + threadIdx.x;
    bool valid = (t < B);
    int e = valid
          ? (s_is64 ? (int)((const long long*)pos)[t] : ((const int*)pos)[t])
          : -1;

    unsigned mm = __match_any_sync(0xffffffffu, e);
    int lane = threadIdx.x & 31;
    int rank = __popc(mm & ((1u << lane) - 1));
    int leader = __ffs(mm) - 1;
    int wbase = 0;
    if (lane == leader && valid) wbase = atomicAdd(&sh[e], __popc(mm));
    wbase = __shfl_sync(0xffffffffu, wbase, leader);
    int r = wbase + rank;

    __syncthreads();
    if (threadIdx.x < N_EXPERTS) {
        int c = sh[threadIdx.x];
        sbase[threadIdx.x] = c ? atomicAdd(&g_cnt[threadIdx.x], c) : 0;
    }
    __syncthreads();
    if (valid) g_bucket[e * MAXB + sbase[e] + r] = t;
}

// ---- kernel 2: main compute ---------------------------------------------
// Output-dim-packed f32x2: weights stored transposed in smem so each k step
// broadcast-loads 4 consecutive output-neuron weights (ulonglong2) and
// updates 16 independent packed accumulators acc[p] = (h[2p], h[2p+1]).
// acc IS the layer output: no cross-half reduction, reused for layer 0.
__global__ void __launch_bounds__(TPB, 3) k_compute(
    const float* __restrict__ x,
    const float* __restrict__ W1, const float* __restrict__ b1,
    const float* __restrict__ W0, const float* __restrict__ b0,
    float* __restrict__ out)
{
    __shared__ __align__(16) float sA[DIM * DIM];   // sA[k*32+o] = W1[o][k]
    __shared__ __align__(16) float sB[DIM * DIM];   // sB[k*32+o] = W0[o][k]
    __shared__ __align__(16) float sb1f[DIM];
    __shared__ __align__(16) float sb0f[DIM];

    // ---- block -> (expert, tile) mapping ----
    int rem = blockIdx.x;
    int e = 0, n = 0;
    #pragma unroll 1
    for (e = 0; e < N_EXPERTS; e++) {
        n = g_cnt[e];
        int nb = (n + TPB - 1) / TPB;
        if (rem < nb) break;
        rem -= nb;
    }
    if (e == N_EXPERTS) return;   // block-uniform, before any sync
    int base = rem * TPB;
    int tid = threadIdx.x;

    // ---- stage weights transposed ----
    #pragma unroll
    for (int i = tid; i < DIM * DIM; i += TPB) {
        int o = i >> 5, k = i & 31;
        sA[k * DIM + o] = W1[e * DIM * DIM + i];
        sB[k * DIM + o] = W0[e * DIM * DIM + i];
    }
    if (tid < DIM) {
        sb1f[tid] = b1[e * DIM + tid];
        sb0f[tid] = b0[e * DIM + tid];
    }
    __syncthreads();

    int slot = base + tid;
    if (slot >= n) return;
    int t = g_bucket[e * MAXB + slot];

    // ---- load x row (one 128B line per thread) ----
    float xr[DIM];
    {
        const float4* xp = (const float4*)(x + (size_t)t * DIM);
        #pragma unroll
        for (int j = 0; j < DIM / 4; j++) {
            float4 v = xp[j];
            xr[4*j+0] = v.x; xr[4*j+1] = v.y; xr[4*j+2] = v.z; xr[4*j+3] = v.w;
        }
    }

    u64 acc[DIM / 2];

    // ---- layer 1: acc[p] = (h[2p], h[2p+1]) ----
    {
        const u64* bp = (const u64*)sb1f;
        #pragma unroll
        for (int p = 0; p < DIM / 2; p++) acc[p] = bp[p];
        const ulonglong2* Ap = (const ulonglong2*)sA;
        #pragma unroll
        for (int k = 0; k < DIM; k++) {
            u64 xk = pk2(xr[k], xr[k]);
            #pragma unroll
            for (int q = 0; q < DIM / 4; q++) {
                ulonglong2 w = Ap[k * (DIM / 4) + q];    // broadcast, 4 neurons
                acc[2*q]     = fma2(w.x, xk, acc[2*q]);
                acc[2*q + 1] = fma2(w.y, xk, acc[2*q + 1]);
            }
        }
        // unpack h into xr (reuse registers)
        #pragma unroll
        for (int p = 0; p < DIM / 2; p++) unpk2(acc[p], xr[2*p], xr[2*p+1]);
    }

    // ---- layer 0: acc[p] = (out[2p], out[2p+1]) ----
    {
        const u64* bp = (const u64*)sb0f;
        #pragma unroll
        for (int p = 0; p < DIM / 2; p++) acc[p] = bp[p];
        const ulonglong2* Bp = (const ulonglong2*)sB;
        #pragma unroll
        for (int k = 0; k < DIM; k++) {
            u64 hk = pk2(xr[k], xr[k]);
            #pragma unroll
            for (int q = 0; q < DIM / 4; q++) {
                ulonglong2 w = Bp[k * (DIM / 4) + q];
                acc[2*q]     = fma2(w.x, hk, acc[2*q]);
                acc[2*q + 1] = fma2(w.y, hk, acc[2*q + 1]);
            }
        }
    }

    // ---- norm ----
    u64 ss2 = 0ull;
    #pragma unroll
    for (int p = 0; p < DIM / 2; p++) ss2 = fma2(acc[p], acc[p], ss2);
    float slo, shi; unpk2(ss2, slo, shi);
    float inv = 1.0f / fmaxf(sqrtf(slo + shi), 1e-12f);

    // ---- scaled store (one 128B line per thread) ----
    float4* op = (float4*)(out + (size_t)t * DIM);
    #pragma unroll
    for (int j = 0; j < DIM / 4; j++) {
        float a0, a1, a2, a3;
        unpk2(acc[2*j],     a0, a1);
        unpk2(acc[2*j + 1], a2, a3);
        float4 v;
        v.x = a0 * inv; v.y = a1 * inv; v.z = a2 * inv; v.w = a3 * inv;
        op[j] = v;
    }
}

// ---------------- launch -------------------------------------------------
extern "C" void kernel_launch(void* const* d_in, const int* in_sizes, int n_in,
                              void* d_out, int out_size) {
    const float* x  = (const float*)d_in[0];
    const float* W1 = (const float*)d_in[1];
    const float* b1 = (const float*)d_in[2];
    const float* W0 = (const float*)d_in[3];
    const float* b0 = (const float*)d_in[4];
    const void*  pos = d_in[5];
    float* out = (float*)d_out;

    int B = in_sizes[0] / DIM;
    if (B > MAXB) B = MAXB;
    int nblk = (B + TPB - 1) / TPB;

    void* cnt_ptr = nullptr;
    cudaGetSymbolAddress(&cnt_ptr, g_cnt);
    cudaMemsetAsync(cnt_ptr, 0, N_EXPERTS * sizeof(int), 0);

    k_bucket<<<nblk, TPB>>>(pos, B);
    k_compute<<<nblk + N_EXPERTS - 1, TPB>>>(x, W1, b1, W0, b0, out);
}

// round 6
// speedup vs baseline: 2.3871x; 1.7371x over previous
#include <cuda_runtime.h>
#include <cuda_bf16.h>
#include <stdint.h>

#define N_EXPERTS 20
#define DIM 32
#define MAXB (1 << 17)     // 131072
#define TPB_B 256
#define TILE 128           // tokens per compute CTA
#define CTPB 128
#define ASTR 72            // A/B tile row stride in bf16 elems (144B, conflict-free)

__device__ int g_cnt[N_EXPERTS];
__device__ int g_bucket[N_EXPERTS * MAXB];

// ---- kernel 1: fused bucket (warp-aggregated hist + claim + write) ------
__global__ void __launch_bounds__(TPB_B) k_bucket(const void* __restrict__ pos, int B) {
    __shared__ int sh[N_EXPERTS];
    __shared__ int sbase[N_EXPERTS];
    __shared__ int s_is64;

    if (threadIdx.x < N_EXPERTS) sh[threadIdx.x] = 0;
    if (threadIdx.x < 32) {
        // int64 pos => all odd 32-bit words are zero high-words (values < 20)
        int v = ((const int*)pos)[2 * threadIdx.x + 1];   // B >= 64 guaranteed
        unsigned nz = __ballot_sync(0xffffffffu, v != 0);
        if (threadIdx.x == 0) s_is64 = (nz == 0) ? 1 : 0;
    }
    __syncthreads();

    int t = blockIdx.x * TPB_B + threadIdx.x;
    bool valid = (t < B);
    int e = valid
          ? (s_is64 ? (int)((const long long*)pos)[t] : ((const int*)pos)[t])
          : -1;

    unsigned mm = __match_any_sync(0xffffffffu, e);
    int lane = threadIdx.x & 31;
    int rank = __popc(mm & ((1u << lane) - 1));
    int leader = __ffs(mm) - 1;
    int wbase = 0;
    if (lane == leader && valid) wbase = atomicAdd(&sh[e], __popc(mm));
    wbase = __shfl_sync(0xffffffffu, wbase, leader);
    int r = wbase + rank;

    __syncthreads();
    if (threadIdx.x < N_EXPERTS) {
        int c = sh[threadIdx.x];
        sbase[threadIdx.x] = c ? atomicAdd(&g_cnt[threadIdx.x], c) : 0;
    }
    __syncthreads();
    if (valid) g_bucket[e * MAXB + sbase[e] + r] = t;
}

// ---- mma.sync wrapper ----------------------------------------------------
__device__ __forceinline__ void mma16816(float* c, const uint32_t* a, const uint32_t* b) {
    asm volatile(
        "mma.sync.aligned.m16n8k16.row.col.f32.bf16.bf16.f32 "
        "{%0,%1,%2,%3}, {%4,%5,%6,%7}, {%8,%9}, {%0,%1,%2,%3};"
        : "+f"(c[0]), "+f"(c[1]), "+f"(c[2]), "+f"(c[3])
        : "r"(a[0]), "r"(a[1]), "r"(a[2]), "r"(a[3]), "r"(b[0]), "r"(b[1]));
}

// split one fp32 into hi/lo bf16
__device__ __forceinline__ void split2(float a, float b, uint32_t& hi, uint32_t& lo) {
    __nv_bfloat162 hp = __floats2bfloat162_rn(a, b);
    float ra = a - __bfloat162float(hp.x);
    float rb = b - __bfloat162float(hp.y);
    __nv_bfloat162 lp = __floats2bfloat162_rn(ra, rb);
    hi = *reinterpret_cast<uint32_t*>(&hp);
    lo = *reinterpret_cast<uint32_t*>(&lp);
}

// ---- kernel 2: HMMA compute ---------------------------------------------
// Per CTA: 128 tokens, one expert. A tile [128][72] bf16: cols 0..31 = hi(x),
// 32..63 = lo(x). W tiles [32 o][72] bf16: cols 0..31 = hi(W[o][k]), 32..63 = lo.
// Layer = A @ W^T via 6 m16n8k16 HMMA per (mtile,ntile): hi.hi(k0,k1),
// lo.hi(k0,k1), hi.lo(k0,k1). Warp w owns rows 32w..32w+31 -> writes its own
// A rows; only one block-wide sync (after weight staging).
__global__ void __launch_bounds__(CTPB) k_compute(
    const float* __restrict__ x,
    const float* __restrict__ W1, const float* __restrict__ b1,
    const float* __restrict__ W0, const float* __restrict__ b0,
    float* __restrict__ out)
{
    __shared__ __align__(16) __nv_bfloat16 sA[TILE * ASTR];      // 18432 B
    __shared__ __align__(16) __nv_bfloat16 sB1[DIM * ASTR];      // 4608 B
    __shared__ __align__(16) __nv_bfloat16 sB2[DIM * ASTR];      // 4608 B
    __shared__ __align__(16) float sb1[DIM], sb0[DIM];
    __shared__ int sTok[TILE];

    // ---- block -> (expert, tile) ----
    int rem = blockIdx.x;
    int e = 0, n = 0;
    #pragma unroll 1
    for (e = 0; e < N_EXPERTS; e++) {
        n = g_cnt[e];
        int nb = (n + TILE - 1) / TILE;
        if (rem < nb) break;
        rem -= nb;
    }
    if (e == N_EXPERTS) return;   // block-uniform, before any sync
    int base = rem * TILE;
    int tid = threadIdx.x;

    // ---- stage weights (hi/lo split) + biases ----
    #pragma unroll 1
    for (int i = tid; i < DIM * DIM; i += CTPB) {
        int o = i >> 5, k = i & 31;
        float w1v = W1[e * DIM * DIM + i];
        __nv_bfloat16 h1 = __float2bfloat16(w1v);
        sB1[o * ASTR + k]      = h1;
        sB1[o * ASTR + 32 + k] = __float2bfloat16(w1v - __bfloat162float(h1));
        float w0v = W0[e * DIM * DIM + i];
        __nv_bfloat16 h0 = __float2bfloat16(w0v);
        sB2[o * ASTR + k]      = h0;
        sB2[o * ASTR + 32 + k] = __float2bfloat16(w0v - __bfloat162float(h0));
    }
    if (tid < DIM) {
        sb1[tid] = b1[e * DIM + tid];
        sb0[tid] = b0[e * DIM + tid];
    }

    // ---- gather token row, split hi/lo into A tile ----
    int slot = base + tid;
    int tok = (slot < n) ? g_bucket[e * MAXB + slot] : -1;
    sTok[tid] = tok;
    {
        float v[DIM];
        #pragma unroll
        for (int j = 0; j < DIM; j++) v[j] = 0.0f;
        if (tok >= 0) {
            const float4* xp = (const float4*)(x + (size_t)tok * DIM);
            #pragma unroll
            for (int j = 0; j < DIM / 4; j++) {
                float4 q = xp[j];
                v[4*j+0] = q.x; v[4*j+1] = q.y; v[4*j+2] = q.z; v[4*j+3] = q.w;
            }
        }
        uint32_t* row = (uint32_t*)(sA + tid * ASTR);
        #pragma unroll
        for (int j = 0; j < 16; j++) split2(v[2*j], v[2*j+1], row[j], row[16 + j]);
    }
    __syncthreads();

    // ---- fragment geometry ----
    int w  = tid >> 5;
    int l  = tid & 31;
    int g  = l >> 2;           // 0..7
    int t4 = l & 3;            // 0..3
    const int kA[6] = {0, 16, 32, 48, 0, 16};
    const int kB[6] = {0, 16, 0, 16, 32, 48};

    float acc[2][4][4];
    uint32_t hfrag[2][4][4];   // bf16x2 h values (hi at [..][0..1]? see below)

    // ======================= layer 1 =======================
    #pragma unroll
    for (int mt = 0; mt < 2; mt++)
        #pragma unroll
        for (int nt = 0; nt < 4; nt++) {
            float2 bv = *(const float2*)&sb1[nt * 8 + 2 * t4];
            acc[mt][nt][0] = bv.x; acc[mt][nt][1] = bv.y;
            acc[mt][nt][2] = bv.x; acc[mt][nt][3] = bv.y;
        }
    #pragma unroll
    for (int ks = 0; ks < 6; ks++) {
        uint32_t bf[4][2];
        #pragma unroll
        for (int nt = 0; nt < 4; nt++) {
            bf[nt][0] = *(const uint32_t*)&sB1[(nt * 8 + g) * ASTR + kB[ks] + 2 * t4];
            bf[nt][1] = *(const uint32_t*)&sB1[(nt * 8 + g) * ASTR + kB[ks] + 2 * t4 + 8];
        }
        #pragma unroll
        for (int mt = 0; mt < 2; mt++) {
            int r0 = w * 32 + mt * 16 + g;
            uint32_t af[4];
            af[0] = *(const uint32_t*)&sA[r0       * ASTR + kA[ks] + 2 * t4];
            af[1] = *(const uint32_t*)&sA[(r0 + 8) * ASTR + kA[ks] + 2 * t4];
            af[2] = *(const uint32_t*)&sA[r0       * ASTR + kA[ks] + 2 * t4 + 8];
            af[3] = *(const uint32_t*)&sA[(r0 + 8) * ASTR + kA[ks] + 2 * t4 + 8];
            #pragma unroll
            for (int nt = 0; nt < 4; nt++) mma16816(acc[mt][nt], af, bf[nt]);
        }
    }

    // write h back into A tile (hi/lo), own rows only
    #pragma unroll
    for (int mt = 0; mt < 2; mt++) {
        int r0 = w * 32 + mt * 16 + g;
        #pragma unroll
        for (int nt = 0; nt < 4; nt++) {
            int c = nt * 8 + 2 * t4;
            uint32_t hi0, lo0, hi1, lo1;
            split2(acc[mt][nt][0], acc[mt][nt][1], hi0, lo0);
            split2(acc[mt][nt][2], acc[mt][nt][3], hi1, lo1);
            *(uint32_t*)&sA[r0 * ASTR + c]            = hi0;
            *(uint32_t*)&sA[r0 * ASTR + 32 + c]       = lo0;
            *(uint32_t*)&sA[(r0 + 8) * ASTR + c]      = hi1;
            *(uint32_t*)&sA[(r0 + 8) * ASTR + 32 + c] = lo1;
        }
    }
    __syncwarp();

    // ======================= layer 0 =======================
    #pragma unroll
    for (int mt = 0; mt < 2; mt++)
        #pragma unroll
        for (int nt = 0; nt < 4; nt++) {
            float2 bv = *(const float2*)&sb0[nt * 8 + 2 * t4];
            acc[mt][nt][0] = bv.x; acc[mt][nt][1] = bv.y;
            acc[mt][nt][2] = bv.x; acc[mt][nt][3] = bv.y;
        }
    #pragma unroll
    for (int ks = 0; ks < 6; ks++) {
        uint32_t bf[4][2];
        #pragma unroll
        for (int nt = 0; nt < 4; nt++) {
            bf[nt][0] = *(const uint32_t*)&sB2[(nt * 8 + g) * ASTR + kB[ks] + 2 * t4];
            bf[nt][1] = *(const uint32_t*)&sB2[(nt * 8 + g) * ASTR + kB[ks] + 2 * t4 + 8];
        }
        #pragma unroll
        for (int mt = 0; mt < 2; mt++) {
            int r0 = w * 32 + mt * 16 + g;
            uint32_t af[4];
            af[0] = *(const uint32_t*)&sA[r0       * ASTR + kA[ks] + 2 * t4];
            af[1] = *(const uint32_t*)&sA[(r0 + 8) * ASTR + kA[ks] + 2 * t4];
            af[2] = *(const uint32_t*)&sA[r0       * ASTR + kA[ks] + 2 * t4 + 8];
            af[3] = *(const uint32_t*)&sA[(r0 + 8) * ASTR + kA[ks] + 2 * t4 + 8];
            #pragma unroll
            for (int nt = 0; nt < 4; nt++) mma16816(acc[mt][nt], af, bf[nt]);
        }
    }

    // ---- epilogue: row sum-of-squares (4-lane bfly), normalize, store ----
    #pragma unroll
    for (int mt = 0; mt < 2; mt++) {
        int r0 = w * 32 + mt * 16 + g;
        float s0 = 0.0f, s1 = 0.0f;
        #pragma unroll
        for (int nt = 0; nt < 4; nt++) {
            s0 = fmaf(acc[mt][nt][0], acc[mt][nt][0], s0);
            s0 = fmaf(acc[mt][nt][1], acc[mt][nt][1], s0);
            s1 = fmaf(acc[mt][nt][2], acc[mt][nt][2], s1);
            s1 = fmaf(acc[mt][nt][3], acc[mt][nt][3], s1);
        }
        s0 += __shfl_xor_sync(0xffffffffu, s0, 1);
        s0 += __shfl_xor_sync(0xffffffffu, s0, 2);
        s1 += __shfl_xor_sync(0xffffffffu, s1, 1);
        s1 += __shfl_xor_sync(0xffffffffu, s1, 2);
        float inv0 = 1.0f / fmaxf(sqrtf(s0), 1e-12f);
        float inv1 = 1.0f / fmaxf(sqrtf(s1), 1e-12f);

        int tok0 = sTok[r0];
        int tok1 = sTok[r0 + 8];
        #pragma unroll
        for (int nt = 0; nt < 4; nt++) {
            int c = nt * 8 + 2 * t4;
            if (tok0 >= 0) {
                float2 v = make_float2(acc[mt][nt][0] * inv0, acc[mt][nt][1] * inv0);
                *(float2*)(out + (size_t)tok0 * DIM + c) = v;
            }
            if (tok1 >= 0) {
                float2 v = make_float2(acc[mt][nt][2] * inv1, acc[mt][nt][3] * inv1);
                *(float2*)(out + (size_t)tok1 * DIM + c) = v;
            }
        }
    }
}

// ---------------- launch -------------------------------------------------
extern "C" void kernel_launch(void* const* d_in, const int* in_sizes, int n_in,
                              void* d_out, int out_size) {
    const float* x  = (const float*)d_in[0];
    const float* W1 = (const float*)d_in[1];
    const float* b1 = (const float*)d_in[2];
    const float* W0 = (const float*)d_in[3];
    const float* b0 = (const float*)d_in[4];
    const void*  pos = d_in[5];
    float* out = (float*)d_out;

    int B = in_sizes[0] / DIM;
    if (B > MAXB) B = MAXB;
    int nblk_b = (B + TPB_B - 1) / TPB_B;
    int nblk_c = (B + TILE - 1) / TILE + N_EXPERTS - 1;

    void* cnt_ptr = nullptr;
    cudaGetSymbolAddress(&cnt_ptr, g_cnt);
    cudaMemsetAsync(cnt_ptr, 0, N_EXPERTS * sizeof(int), 0);

    k_bucket<<<nblk_b, TPB_B>>>(pos, B);
    k_compute<<<nblk_c, CTPB>>>(x, W1, b1, W0, b0, out);
}